// round 9
// baseline (speedup 1.0000x reference)
#include <cuda_runtime.h>
#include <cuda_bf16.h>
#include <math.h>

#define NB 64
#define NP 24564
#define NM 16
#define NC 21
#define TPB 256
#define NBLK ((NP + TPB - 1) / TPB)   // 96
#define NHB 4096                      // hist bins (top-12 float bits)
#define GSEG 6                        // gather segments per batch

// ---------------- device scratch ----------------
__device__ unsigned long long g_winner[NB * NM];   // packed (iou_bits<<32)|(~prior)
__device__ float              g_mined[NB * NP];    // mined conf loss (0 at positives)
__device__ unsigned           g_hist[NB * NHB];    // per-batch 12-bit histograms
__device__ float              g_cand[NB * NP];     // threshold-bin candidates
__device__ int                g_cnt[NB];           // candidate counts
__device__ double             g_sumhi[NB];         // sum of values in bins > B
__device__ int                g_selB[NB], g_selkr[NB];
__device__ int                g_num_pos[NB];
__device__ unsigned           g_done;
__device__ double             g_loss_l;
__device__ double             g_loss_c;

// ---------- cp.async helpers ----------
__device__ __forceinline__ void cp_async16(void* smem, const void* gmem) {
    unsigned s = (unsigned)__cvta_generic_to_shared(smem);
    asm volatile("cp.async.cg.shared.global [%0], [%1], 16;\n" :: "r"(s), "l"(gmem));
}
#define CP_COMMIT() asm volatile("cp.async.commit_group;\n" ::: "memory")
#define CP_WAIT0()  asm volatile("cp.async.wait_group 0;\n" ::: "memory")

// ---------- shared exact-math helpers (identical in k_fused / k_force) ----------
__device__ __forceinline__ void prior_corners(float4 pr, float& x1, float& y1,
                                              float& x2, float& y2, float& pa) {
    float hz = __fmul_rn(pr.z, 0.5f), hw = __fmul_rn(pr.w, 0.5f);
    x1 = __fsub_rn(pr.x, hz); y1 = __fsub_rn(pr.y, hw);
    x2 = __fadd_rn(pr.x, hz); y2 = __fadd_rn(pr.y, hw);
    pa = __fmul_rn(__fsub_rn(x2, x1), __fsub_rn(y2, y1));
}

__device__ __forceinline__ float iou_fast(float px1, float py1, float px2, float py2,
                                          float pa, float4 tb, float ta) {
    float ix = fmaxf(__fsub_rn(fminf(px2, tb.z), fmaxf(px1, tb.x)), 0.0f);
    float iy = fmaxf(__fsub_rn(fminf(py2, tb.w), fmaxf(py1, tb.y)), 0.0f);
    float inter = __fmul_rn(ix, iy);
    float uni = __fsub_rn(__fadd_rn(pa, ta), inter);
    return __fdividef(inter, uni);
}

__device__ __forceinline__ float sl1e(float d) {
    float a = fabsf(d);
    return (a < 1.0f) ? __fmul_rn(0.5f, __fmul_rn(d, d)) : __fsub_rn(a, 0.5f);
}

__device__ __forceinline__ float loc_loss(const float4 lp, const float4 pr, float4 tb) {
    float gx = __fdividef(__fsub_rn(__fmul_rn(__fadd_rn(tb.x, tb.z), 0.5f), pr.x),
                          __fmul_rn(0.1f, pr.z));
    float gy = __fdividef(__fsub_rn(__fmul_rn(__fadd_rn(tb.y, tb.w), 0.5f), pr.y),
                          __fmul_rn(0.1f, pr.w));
    float gw = __fdividef(__logf(__fdividef(__fsub_rn(tb.z, tb.x), pr.z)), 0.2f);
    float gh = __fdividef(__logf(__fdividef(__fsub_rn(tb.w, tb.y), pr.w)), 0.2f);
    return __fadd_rn(__fadd_rn(sl1e(__fsub_rn(lp.x, gx)), sl1e(__fsub_rn(lp.y, gy))),
                     __fadd_rn(sl1e(__fsub_rn(lp.z, gw)), sl1e(__fsub_rn(lp.w, gh))));
}

__device__ __forceinline__ float lse21(const float* v) {
    float mx = v[0];
#pragma unroll
    for (int c = 1; c < NC; c++) mx = fmaxf(mx, v[c]);
    float s = 0.0f;
#pragma unroll
    for (int c = 0; c < NC; c++) s = __fadd_rn(s, __expf(__fsub_rn(v[c], mx)));
    return __fadd_rn(mx, __logf(s));
}

// ---------------- kernel A: init ----------------
__global__ void k_init() {
    int i = blockIdx.x * blockDim.x + threadIdx.x;
    if (i < NB * NHB) g_hist[i] = 0u;
    if (i < NB * NM) g_winner[i] = 0ull;
    if (i < NB) { g_num_pos[i] = 0; g_cnt[i] = 0; g_sumhi[i] = 0.0; }
    if (i == 0) { g_loss_l = 0.0; g_loss_c = 0.0; g_done = 0u; }
}

// ---------------- kernel B: FUSED match + LSE + losses + histogram ----------------
__global__ void __launch_bounds__(TPB)
k_fused(const float* __restrict__ loc,
        const float* __restrict__ conf,
        const float* __restrict__ priors,
        const float* __restrict__ targets) {
    const int n   = blockIdx.y;
    const int tid = threadIdx.x;
    const int rb  = blockIdx.x * TPB;
    const int lane = tid & 31;

    __shared__ float4 t_box[NM];          // {x1,y1,x2,y2}
    __shared__ float  t_area[NM], t_lab[NM];
    __shared__ unsigned long long sh_key[NM];
    __shared__ float sbuf[TPB * NC];
    __shared__ float s_ll, s_plc; __shared__ int s_np;

    if (tid < NM) {
        const float* tp = targets + (size_t)(n * NM + tid) * 5;
        float x1 = tp[0], y1 = tp[1], x2 = tp[2], y2 = tp[3];
        t_box[tid] = make_float4(x1, y1, x2, y2);
        t_area[tid] = __fmul_rn(__fsub_rn(x2, x1), __fsub_rn(y2, y1));
        t_lab[tid] = tp[4];
        sh_key[tid] = 0ull;
    }
    if (tid == 0) { s_ll = 0.0f; s_plc = 0.0f; s_np = 0; }
    __syncthreads();                       // targets visible (fast: tiny loads)

    // issue async conf staging; it flies while we do the match phase
    const int rows = min(TPB, NP - rb);
    const int nf4  = rows * NC / 4;
    const float4* src = (const float4*)(conf + ((size_t)n * NP + rb) * NC);
    for (int i = tid; i < nf4; i += TPB)
        cp_async16(((float4*)sbuf) + i, src + i);
    CP_COMMIT();

    const int p = rb + tid;
    const bool valid = tid < rows;

    // ---- match phase (overlaps the cp.async traffic) ----
    float px1 = 0.f, py1 = 0.f, px2 = 0.f, py2 = 0.f, pa = 1.f;
    if (valid) {
        float4 pr = ((const float4*)priors)[p];
        prior_corners(pr, px1, py1, px2, py2, pa);
    }
    float best_ov = -1.0f; int best_t = 0;
#pragma unroll
    for (int t = 0; t < NM; t++) {
        float iou = 0.0f;
        if (valid) {
            iou = iou_fast(px1, py1, px2, py2, pa, t_box[t], t_area[t]);
            if (iou > best_ov) { best_ov = iou; best_t = t; }
        }
        unsigned b    = __float_as_uint(iou);
        unsigned wmax = __reduce_max_sync(0xFFFFFFFFu, b);
        if (valid && b == wmax && b != 0u) {      // ties resolved by atomicMax key
            atomicMax(&sh_key[t],
                      ((unsigned long long)wmax << 32) |
                      (unsigned long long)(0xFFFFFFFFu - (unsigned)p));
        }
    }

    CP_WAIT0();
    __syncthreads();                       // conf staged

    // ---- loss phase ----
    float local_ll = 0.0f, local_plc = 0.0f;
    int   local_np = 0;
    float mined = 0.0f;
    if (valid) {
        int conf_t = (best_ov < 0.5f) ? 0 : ((int)t_lab[best_t] + 1);
        bool pos = conf_t > 0;

        const float* v = sbuf + tid * NC;
        float lse = lse21(v);
        float lc  = __fsub_rn(lse, v[conf_t]);

        mined = pos ? 0.0f : lc;
        g_mined[(size_t)n * NP + p] = mined;

        if (pos) {
            local_np  = 1;
            local_plc = lc;
            float4 pr = ((const float4*)priors)[p];
            float4 lp = ((const float4*)loc)[(size_t)n * NP + p];
            local_ll = loc_loss(lp, pr, t_box[best_t]);
        }
    }

    // per-batch 12-bit histogram (warp-aggregated)
    {
        unsigned hv = valid ? (__float_as_uint(mined) >> 20) : 0xFFFFu;
        unsigned peers = __match_any_sync(0xFFFFFFFFu, hv);
        if (hv < NHB && lane == (__ffs(peers) - 1))
            atomicAdd(&g_hist[n * NHB + hv], (unsigned)__popc(peers));
    }

#pragma unroll
    for (int o = 16; o; o >>= 1) {
        local_ll  += __shfl_down_sync(0xFFFFFFFFu, local_ll,  o);
        local_plc += __shfl_down_sync(0xFFFFFFFFu, local_plc, o);
        local_np  += __shfl_down_sync(0xFFFFFFFFu, local_np,  o);
    }
    __syncthreads();
    if (lane == 0) {
        if (local_ll  != 0.0f) atomicAdd(&s_ll,  local_ll);
        if (local_plc != 0.0f) atomicAdd(&s_plc, local_plc);
        if (local_np)          atomicAdd(&s_np,  local_np);
    }
    __syncthreads();
    if (tid < NM && sh_key[tid])
        atomicMax(&g_winner[n * NM + tid], sh_key[tid]);
    if (tid == 0) {
        if (s_np)          atomicAdd(&g_num_pos[n], s_np);
        if (s_ll  != 0.0f) atomicAdd(&g_loss_l, (double)s_ll);
        if (s_plc != 0.0f) atomicAdd(&g_loss_c, (double)s_plc);
    }
}

// ---------------- kernel C: forced corrections + threshold-bin selection ----------------
// warp per batch (2 blocks x 32 warps). After corrections, the same warp scans
// its batch's 4096-bin hist and emits (selB, selkr).
__global__ void k_force(const float* __restrict__ loc,
                        const float* __restrict__ conf,
                        const float* __restrict__ priors,
                        const float* __restrict__ targets) {
    const int tid  = threadIdx.x;
    const int lane = tid & 31;
    const int warp = tid >> 5;
    const int n    = blockIdx.x * 32 + warp;   // always < NB with <<<2,1024>>>

    __shared__ float4 w_box[32][NM];
    __shared__ float  w_ar[32][NM], w_lb[32][NM];

    if (lane < NM) {
        const float* tp = targets + (size_t)(n * NM + lane) * 5;
        float x1 = tp[0], y1 = tp[1], x2 = tp[2], y2 = tp[3];
        w_box[warp][lane] = make_float4(x1, y1, x2, y2);
        w_ar[warp][lane] = __fmul_rn(__fsub_rn(x2, x1), __fsub_rn(y2, y1));
        w_lb[warp][lane] = tp[4];
    }
    __syncwarp();

    float dll = 0.0f, dlc = 0.0f;
    int   dnp = 0;

    if (lane < NM) {
        unsigned long long w = g_winner[n * NM + lane];
        unsigned p = 0xFFFFFFFFu - (unsigned)(w & 0xFFFFFFFFull);

        unsigned peers = __match_any_sync(0x0000FFFFu, p);
        bool firstOcc = (lane == (__ffs(peers) - 1));
        bool isLast   = (lane == (31 - __clz(peers)));   // last truth wins

        float4 pr = ((const float4*)priors)[p];
        float px1, py1, px2, py2, pa;
        prior_corners(pr, px1, py1, px2, py2, pa);

        const float* row = conf + ((size_t)n * NP + p) * NC;
        float v[NC];
#pragma unroll
        for (int c = 0; c < NC; c++) v[c] = row[c];
        float lse = lse21(v);

        if (firstOcc) {
            float best_ov = -1.0f; int best_t = 0;
#pragma unroll
            for (int t = 0; t < NM; t++) {
                float iou = iou_fast(px1, py1, px2, py2, pa, w_box[warp][t], w_ar[warp][t]);
                if (iou > best_ov) { best_ov = iou; best_t = t; }
            }
            int conf_t0 = (best_ov < 0.5f) ? 0 : ((int)w_lb[warp][best_t] + 1);
            if (conf_t0 > 0) {
                dlc -= __fsub_rn(lse, v[conf_t0]);
                float4 lp = ((const float4*)loc)[(size_t)n * NP + p];
                dll -= loc_loss(lp, pr, w_box[warp][best_t]);
            } else {
                dnp += 1;
                // hist fixup: lc_old leaves its bin, a zero enters bin 0
                float lc_old = __fsub_rn(lse, v[0]);
                atomicAdd(&g_hist[n * NHB + (__float_as_uint(lc_old) >> 20)], 0xFFFFFFFFu);
                atomicAdd(&g_hist[n * NHB + 0], 1u);
            }
            g_mined[(size_t)n * NP + p] = 0.0f;
        }
        if (isLast) {
            int ct = (int)w_lb[warp][lane] + 1;
            dlc += __fsub_rn(lse, v[ct]);
            float4 lp = ((const float4*)loc)[(size_t)n * NP + p];
            dll += loc_loss(lp, pr, w_box[warp][lane]);
        }
    }

#pragma unroll
    for (int o = 16; o; o >>= 1) {
        dll += __shfl_down_sync(0xFFFFFFFFu, dll, o);
        dlc += __shfl_down_sync(0xFFFFFFFFu, dlc, o);
        dnp += __shfl_down_sync(0xFFFFFFFFu, dnp, o);
    }
    int kf = 0;
    if (lane == 0) {
        if (dll != 0.0f) atomicAdd(&g_loss_l, (double)dll);
        if (dlc != 0.0f) atomicAdd(&g_loss_c, (double)dlc);
        int npv = g_num_pos[n];                 // sole writer for batch n here
        if (dnp) g_num_pos[n] = npv + dnp;
        kf = min(3 * (npv + dnp), NP - 1);
    }
    kf = __shfl_sync(0xFFFFFFFFu, kf, 0);

    // ---- threshold-bin selection: warp suffix-scan over 4096 bins ----
    // (shfl reductions above synchronized the warp; hist reads use __ldcg = L2)
    const unsigned* hrow = g_hist + n * NHB;
    const int base = lane * 128;
    int c = 0;
#pragma unroll 8
    for (int j = 0; j < 128; j++) c += (int)__ldcg(&hrow[base + j]);
    int s = c;
#pragma unroll
    for (int o = 1; o < 32; o <<= 1) {
        int t = __shfl_down_sync(0xFFFFFFFFu, s, o);
        if (lane + o < 32) s += t;
    }
    // broadcast not needed: each lane needs only its own suffix
    int running = __shfl_down_sync(0xFFFFFFFFu, s, 1);     // Σ_{m>lane}
    if (lane == 31) running = 0;
    for (int j = 127; j >= 0; j--) {
        int hv = (int)__ldcg(&hrow[base + j]);
        if (running < kf && running + hv >= kf) {
            g_selB[n]  = base + j;
            g_selkr[n] = kf - running;
        }
        running += hv;
    }
}

// ---------------- kernel D: gather — sum high bins, collect threshold bin ----------------
__global__ void k_gather() {     // grid (GSEG, NB) x 1024
    const int n   = blockIdx.y;
    const int tid = threadIdx.x;
    const int B   = g_selB[n];
    const int start = blockIdx.x * 4096;
    const int end   = min(start + 4096, NP);

    double local = 0.0;
    for (int i = start + tid; i < end; i += 1024) {
        float f = g_mined[(size_t)n * NP + i];
        unsigned b = __float_as_uint(f) >> 20;
        if ((int)b > B) local += (double)f;
        else if ((int)b == B) {
            int idx = atomicAdd(&g_cnt[n], 1);
            g_cand[(size_t)n * NP + idx] = f;
        }
    }
#pragma unroll
    for (int o = 16; o; o >>= 1)
        local += __shfl_down_sync(0xFFFFFFFFu, local, o);
    __shared__ double s_sum;
    if (tid == 0) s_sum = 0.0;
    __syncthreads();
    if ((tid & 31) == 0 && local != 0.0) atomicAdd(&s_sum, local);
    __syncthreads();
    if (tid == 0 && s_sum != 0.0) atomicAdd(&g_sumhi[n], s_sum);
}

// ---------------- kernel E: kr-th largest among candidates + final output ----------------
__global__ void k_sel2(float* out, int out_size) {   // 64 blocks x 256 threads
    const int n = blockIdx.x, tid = threadIdx.x;
    const int ncand = g_cnt[n];
    const int B = g_selB[n];
    int kr = g_selkr[n];

    __shared__ int hist[256];
    __shared__ unsigned s_pref; __shared__ int s_kr;

    unsigned prefix = (unsigned)B;            // top-12 bits established
    const int shifts[3] = {12, 4, 0};
    const int widths[3] = {8, 8, 4};
    for (int pass = 0; pass < 3; pass++) {
        const int sh = shifts[pass], wd = widths[pass];
        const unsigned mask = (1u << wd) - 1u;
        if (tid < 256) hist[tid] = 0;
        __syncthreads();
        for (int i = tid; i < ncand; i += 256) {
            unsigned bits = __float_as_uint(g_cand[(size_t)n * NP + i]);
            if ((bits >> (sh + wd)) == prefix)
                atomicAdd(&hist[(bits >> sh) & mask], 1);
        }
        __syncthreads();
        if (tid == 0) {
            int acc = 0, d = (int)mask;
            for (; d > 0; d--) { if (acc + hist[d] >= kr) break; acc += hist[d]; }
            s_pref = (prefix << wd) | (unsigned)d;
            s_kr   = kr - acc;
        }
        __syncthreads();
        prefix = s_pref; kr = s_kr;
        __syncthreads();
    }

    const float u = __uint_as_float(prefix);
    float sum_gt = 0.0f;
    for (int i = tid; i < ncand; i += 256) {
        float f = g_cand[(size_t)n * NP + i];
        if (f > u) sum_gt += f;
    }
#pragma unroll
    for (int o = 16; o; o >>= 1)
        sum_gt += __shfl_down_sync(0xFFFFFFFFu, sum_gt, o);
    __shared__ float s_sg;
    __shared__ bool s_last;
    if (tid == 0) s_sg = 0.0f;
    __syncthreads();
    if ((tid & 31) == 0 && sum_gt != 0.0f) atomicAdd(&s_sg, sum_gt);
    __syncthreads();
    if (tid == 0) {
        double S = g_sumhi[n] + (double)s_sg + (double)kr * (double)u;
        atomicAdd(&g_loss_c, S);
        __threadfence();
        unsigned d = atomicAdd(&g_done, 1u);
        s_last = (d == NB - 1);
    }
    __syncthreads();
    if (s_last && tid == 0) {                 // last block finalizes
        int ntot = 0;
        for (int i = 0; i < NB; i++) ntot += g_num_pos[i];
        double nf = (double)ntot;
        out[0] = (float)(g_loss_l / nf);
        if (out_size > 1) out[1] = (float)(g_loss_c / nf);
    }
}

// ---------------- launch ----------------
extern "C" void kernel_launch(void* const* d_in, const int* in_sizes, int n_in,
                              void* d_out, int out_size) {
    const float* loc     = (const float*)d_in[0];
    const float* conf    = (const float*)d_in[1];
    const float* priors  = (const float*)d_in[2];
    const float* targets = (const float*)d_in[3];
    float* out = (float*)d_out;

    dim3 grid(NBLK, NB);
    k_init<<<(NB * NHB + 255) / 256, 256>>>();
    k_fused<<<grid, TPB>>>(loc, conf, priors, targets);
    k_force<<<2, 1024>>>(loc, conf, priors, targets);
    k_gather<<<dim3(GSEG, NB), 1024>>>();
    k_sel2<<<NB, 256>>>(out, out_size);
}

// round 10
// speedup vs baseline: 1.3044x; 1.3044x over previous
#include <cuda_runtime.h>
#include <cuda_bf16.h>
#include <math.h>

#define NB 64
#define NP 24564
#define NM 16
#define NC 21
#define TPB 256
#define NBLK ((NP + TPB - 1) / TPB)   // 96
#define NHB 4096                      // hist bins (top-12 float bits)
#define GSEG 6                        // gather segments per batch
#define GCH 4096                      // elements per gather block

// ---------------- device scratch ----------------
__device__ unsigned long long g_winner[NB * NM];   // packed (iou_bits<<32)|(~prior)
__device__ float              g_mined[NB * NP];    // mined conf loss (0 at positives)
__device__ unsigned           g_hist[NB * NHB];    // per-batch 12-bit histograms
__device__ float              g_cand[NB * NP];     // threshold-bin candidates
__device__ int                g_cnt[NB];           // candidate counts
__device__ double             g_sumhi[NB];         // sum of values in bins > B
__device__ int                g_selB[NB], g_selkr[NB];
__device__ int                g_num_pos[NB];
__device__ unsigned           g_done;
__device__ double             g_loss_l;
__device__ double             g_loss_c;

// ---------- shared exact-math helpers (identical in k_fused / k_force) ----------
__device__ __forceinline__ void prior_corners(float4 pr, float& x1, float& y1,
                                              float& x2, float& y2, float& pa) {
    float hz = __fmul_rn(pr.z, 0.5f), hw = __fmul_rn(pr.w, 0.5f);
    x1 = __fsub_rn(pr.x, hz); y1 = __fsub_rn(pr.y, hw);
    x2 = __fadd_rn(pr.x, hz); y2 = __fadd_rn(pr.y, hw);
    pa = __fmul_rn(__fsub_rn(x2, x1), __fsub_rn(y2, y1));
}

__device__ __forceinline__ float iou_fast(float px1, float py1, float px2, float py2,
                                          float pa, float4 tb, float ta) {
    float ix = fmaxf(__fsub_rn(fminf(px2, tb.z), fmaxf(px1, tb.x)), 0.0f);
    float iy = fmaxf(__fsub_rn(fminf(py2, tb.w), fmaxf(py1, tb.y)), 0.0f);
    float inter = __fmul_rn(ix, iy);
    float uni = __fsub_rn(__fadd_rn(pa, ta), inter);
    return __fdividef(inter, uni);
}

__device__ __forceinline__ float sl1e(float d) {
    float a = fabsf(d);
    return (a < 1.0f) ? __fmul_rn(0.5f, __fmul_rn(d, d)) : __fsub_rn(a, 0.5f);
}

__device__ __forceinline__ float loc_loss(const float4 lp, const float4 pr, float4 tb) {
    float gx = __fdividef(__fsub_rn(__fmul_rn(__fadd_rn(tb.x, tb.z), 0.5f), pr.x),
                          __fmul_rn(0.1f, pr.z));
    float gy = __fdividef(__fsub_rn(__fmul_rn(__fadd_rn(tb.y, tb.w), 0.5f), pr.y),
                          __fmul_rn(0.1f, pr.w));
    float gw = __fdividef(__logf(__fdividef(__fsub_rn(tb.z, tb.x), pr.z)), 0.2f);
    float gh = __fdividef(__logf(__fdividef(__fsub_rn(tb.w, tb.y), pr.w)), 0.2f);
    return __fadd_rn(__fadd_rn(sl1e(__fsub_rn(lp.x, gx)), sl1e(__fsub_rn(lp.y, gy))),
                     __fadd_rn(sl1e(__fsub_rn(lp.z, gw)), sl1e(__fsub_rn(lp.w, gh))));
}

__device__ __forceinline__ float lse21(const float* v) {
    float mx = v[0];
#pragma unroll
    for (int c = 1; c < NC; c++) mx = fmaxf(mx, v[c]);
    float s = 0.0f;
#pragma unroll
    for (int c = 0; c < NC; c++) s = __fadd_rn(s, __expf(__fsub_rn(v[c], mx)));
    return __fadd_rn(mx, __logf(s));
}

// ---------------- kernel A: init ----------------
__global__ void k_init() {
    int i = blockIdx.x * blockDim.x + threadIdx.x;
    if (i < NB * NHB) g_hist[i] = 0u;
    if (i < NB * NM) g_winner[i] = 0ull;
    if (i < NB) { g_num_pos[i] = 0; g_cnt[i] = 0; g_sumhi[i] = 0.0; }
    if (i == 0) { g_loss_l = 0.0; g_loss_c = 0.0; g_done = 0u; }
}

// ---------------- kernel B: FUSED match + LSE + losses + histogram (round-8 proven) ----------------
__global__ void __launch_bounds__(TPB)
k_fused(const float* __restrict__ loc,
        const float* __restrict__ conf,
        const float* __restrict__ priors,
        const float* __restrict__ targets) {
    const int n   = blockIdx.y;
    const int tid = threadIdx.x;
    const int rb  = blockIdx.x * TPB;
    const int lane = tid & 31;

    __shared__ float4 t_box[NM];
    __shared__ float  t_area[NM], t_lab[NM];
    __shared__ unsigned long long sh_key[NM];
    __shared__ float sbuf[TPB * NC];
    __shared__ float s_ll, s_plc; __shared__ int s_np;

    if (tid < NM) {
        const float* tp = targets + (size_t)(n * NM + tid) * 5;
        float x1 = tp[0], y1 = tp[1], x2 = tp[2], y2 = tp[3];
        t_box[tid] = make_float4(x1, y1, x2, y2);
        t_area[tid] = __fmul_rn(__fsub_rn(x2, x1), __fsub_rn(y2, y1));
        t_lab[tid] = tp[4];
        sh_key[tid] = 0ull;
    }
    if (tid == 0) { s_ll = 0.0f; s_plc = 0.0f; s_np = 0; }

    const int rows = min(TPB, NP - rb);
    const int nf4  = rows * NC / 4;
    const float4* src = (const float4*)(conf + ((size_t)n * NP + rb) * NC);
    float4* dst = (float4*)sbuf;
    for (int i = tid; i < nf4; i += TPB) dst[i] = src[i];
    __syncthreads();

    const int p = rb + tid;
    const bool valid = tid < rows;

    float px1 = 0.f, py1 = 0.f, px2 = 0.f, py2 = 0.f, pa = 1.f;
    if (valid) {
        float4 pr = ((const float4*)priors)[p];
        prior_corners(pr, px1, py1, px2, py2, pa);
    }
    float best_ov = -1.0f; int best_t = 0;
#pragma unroll
    for (int t = 0; t < NM; t++) {
        float iou = 0.0f;
        if (valid) {
            iou = iou_fast(px1, py1, px2, py2, pa, t_box[t], t_area[t]);
            if (iou > best_ov) { best_ov = iou; best_t = t; }
        }
        unsigned b    = __float_as_uint(iou);
        unsigned wmax = __reduce_max_sync(0xFFFFFFFFu, b);
        if (valid && b == wmax && b != 0u) {      // ties resolved by atomicMax key
            atomicMax(&sh_key[t],
                      ((unsigned long long)wmax << 32) |
                      (unsigned long long)(0xFFFFFFFFu - (unsigned)p));
        }
    }

    float local_ll = 0.0f, local_plc = 0.0f;
    int   local_np = 0;
    float mined = 0.0f;
    if (valid) {
        int conf_t = (best_ov < 0.5f) ? 0 : ((int)t_lab[best_t] + 1);
        bool pos = conf_t > 0;

        const float* v = sbuf + tid * NC;
        float lse = lse21(v);
        float lc  = __fsub_rn(lse, v[conf_t]);

        mined = pos ? 0.0f : lc;
        g_mined[(size_t)n * NP + p] = mined;

        if (pos) {
            local_np  = 1;
            local_plc = lc;
            float4 pr = ((const float4*)priors)[p];
            float4 lp = ((const float4*)loc)[(size_t)n * NP + p];
            local_ll = loc_loss(lp, pr, t_box[best_t]);
        }
    }

    {
        unsigned hv = valid ? (__float_as_uint(mined) >> 20) : 0xFFFFu;
        unsigned peers = __match_any_sync(0xFFFFFFFFu, hv);
        if (hv < NHB && lane == (__ffs(peers) - 1))
            atomicAdd(&g_hist[n * NHB + hv], (unsigned)__popc(peers));
    }

#pragma unroll
    for (int o = 16; o; o >>= 1) {
        local_ll  += __shfl_down_sync(0xFFFFFFFFu, local_ll,  o);
        local_plc += __shfl_down_sync(0xFFFFFFFFu, local_plc, o);
        local_np  += __shfl_down_sync(0xFFFFFFFFu, local_np,  o);
    }
    __syncthreads();
    if (lane == 0) {
        if (local_ll  != 0.0f) atomicAdd(&s_ll,  local_ll);
        if (local_plc != 0.0f) atomicAdd(&s_plc, local_plc);
        if (local_np)          atomicAdd(&s_np,  local_np);
    }
    __syncthreads();
    if (tid < NM && sh_key[tid])
        atomicMax(&g_winner[n * NM + tid], sh_key[tid]);
    if (tid == 0) {
        if (s_np)          atomicAdd(&g_num_pos[n], s_np);
        if (s_ll  != 0.0f) atomicAdd(&g_loss_l, (double)s_ll);
        if (s_plc != 0.0f) atomicAdd(&g_loss_c, (double)s_plc);
    }
}

// ---------------- kernel C: forced-match corrections (round-8 proven, no scan) ----------------
__global__ void k_force(const float* __restrict__ loc,
                        const float* __restrict__ conf,
                        const float* __restrict__ priors,
                        const float* __restrict__ targets) {
    const int tid  = threadIdx.x;
    const int lane = tid & 31;
    const int warp = tid >> 5;
    const int n    = blockIdx.x * 32 + warp;

    __shared__ float4 w_box[32][NM];
    __shared__ float  w_ar[32][NM], w_lb[32][NM];

    if (n < NB && lane < NM) {
        const float* tp = targets + (size_t)(n * NM + lane) * 5;
        float x1 = tp[0], y1 = tp[1], x2 = tp[2], y2 = tp[3];
        w_box[warp][lane] = make_float4(x1, y1, x2, y2);
        w_ar[warp][lane] = __fmul_rn(__fsub_rn(x2, x1), __fsub_rn(y2, y1));
        w_lb[warp][lane] = tp[4];
    }
    __syncwarp();

    float dll = 0.0f, dlc = 0.0f;
    int   dnp = 0;

    if (n < NB && lane < NM) {
        unsigned long long w = g_winner[n * NM + lane];
        unsigned p = 0xFFFFFFFFu - (unsigned)(w & 0xFFFFFFFFull);

        unsigned peers = __match_any_sync(0x0000FFFFu, p);
        bool firstOcc = (lane == (__ffs(peers) - 1));
        bool isLast   = (lane == (31 - __clz(peers)));   // last truth wins

        float4 pr = ((const float4*)priors)[p];
        float px1, py1, px2, py2, pa;
        prior_corners(pr, px1, py1, px2, py2, pa);

        const float* row = conf + ((size_t)n * NP + p) * NC;
        float v[NC];
#pragma unroll
        for (int c = 0; c < NC; c++) v[c] = row[c];
        float lse = lse21(v);

        if (firstOcc) {
            float best_ov = -1.0f; int best_t = 0;
#pragma unroll
            for (int t = 0; t < NM; t++) {
                float iou = iou_fast(px1, py1, px2, py2, pa, w_box[warp][t], w_ar[warp][t]);
                if (iou > best_ov) { best_ov = iou; best_t = t; }
            }
            int conf_t0 = (best_ov < 0.5f) ? 0 : ((int)w_lb[warp][best_t] + 1);
            if (conf_t0 > 0) {
                dlc -= __fsub_rn(lse, v[conf_t0]);
                float4 lp = ((const float4*)loc)[(size_t)n * NP + p];
                dll -= loc_loss(lp, pr, w_box[warp][best_t]);
            } else {
                dnp += 1;
                float lc_old = __fsub_rn(lse, v[0]);
                atomicAdd(&g_hist[n * NHB + (__float_as_uint(lc_old) >> 20)], 0xFFFFFFFFu);
                atomicAdd(&g_hist[n * NHB + 0], 1u);
            }
            g_mined[(size_t)n * NP + p] = 0.0f;
        }
        if (isLast) {
            int ct = (int)w_lb[warp][lane] + 1;
            dlc += __fsub_rn(lse, v[ct]);
            float4 lp = ((const float4*)loc)[(size_t)n * NP + p];
            dll += loc_loss(lp, pr, w_box[warp][lane]);
        }
    }

#pragma unroll
    for (int o = 16; o; o >>= 1) {
        dll += __shfl_down_sync(0xFFFFFFFFu, dll, o);
        dlc += __shfl_down_sync(0xFFFFFFFFu, dlc, o);
        dnp += __shfl_down_sync(0xFFFFFFFFu, dnp, o);
    }
    if (lane == 0 && n < NB) {
        if (dll != 0.0f) atomicAdd(&g_loss_l, (double)dll);
        if (dlc != 0.0f) atomicAdd(&g_loss_c, (double)dlc);
        if (dnp)         atomicAdd(&g_num_pos[n], dnp);
    }
}

// ---------------- kernel D: find threshold bin B + residual kr (round-8 proven) ----------------
__global__ void k_sel() {        // 64 blocks x 256 threads
    const int n = blockIdx.x, tid = threadIdx.x;
    __shared__ unsigned h[NHB];
    __shared__ int csum[256];

    for (int i = tid; i < NHB; i += 256) h[i] = g_hist[n * NHB + i];
    __syncthreads();

    int c = 0;
#pragma unroll
    for (int j = 0; j < 16; j++) c += (int)h[tid * 16 + j];
    csum[tid] = c;
    __syncthreads();
    for (int off = 1; off < 256; off <<= 1) {          // inclusive suffix scan
        int add = (tid + off < 256) ? csum[tid + off] : 0;
        __syncthreads();
        csum[tid] += add;
        __syncthreads();
    }

    const int k = min(3 * g_num_pos[n], NP - 1);
    int running = csum[tid] - c;
    for (int j = 15; j >= 0; j--) {
        int E = running;
        running += (int)h[tid * 16 + j];
        if (E < k && running >= k) {
            g_selB[n]  = tid * 16 + j;
            g_selkr[n] = k - E;
        }
    }
}

// ---------------- kernel E: gather (FIXED: block-local candidate staging) ----------------
__global__ void k_gather() {     // grid (GSEG, NB) x 1024
    const int n   = blockIdx.y;
    const int tid = threadIdx.x;
    const int B   = g_selB[n];
    const int start = blockIdx.x * GCH;
    const int end   = min(start + GCH, NP);

    __shared__ float cbuf[GCH];           // block-local candidates
    __shared__ int s_cnt, s_base;
    __shared__ double s_sum;
    if (tid == 0) { s_cnt = 0; s_sum = 0.0; }
    __syncthreads();

    double local = 0.0;
    for (int i = start + tid; i < end; i += 1024) {
        float f = g_mined[(size_t)n * NP + i];
        unsigned b = __float_as_uint(f) >> 20;
        if ((int)b > B) local += (double)f;
        else if ((int)b == B) {
            int idx = atomicAdd(&s_cnt, 1);          // SMEM atomic (cheap)
            cbuf[idx] = f;
        }
    }
#pragma unroll
    for (int o = 16; o; o >>= 1)
        local += __shfl_down_sync(0xFFFFFFFFu, local, o);
    if ((tid & 31) == 0 && local != 0.0) atomicAdd(&s_sum, local);
    __syncthreads();

    if (tid == 0) {
        if (s_sum != 0.0) atomicAdd(&g_sumhi[n], s_sum);
        s_base = (s_cnt > 0) ? atomicAdd(&g_cnt[n], s_cnt) : 0;   // ONE global atomic
    }
    __syncthreads();
    for (int i = tid; i < s_cnt; i += 1024)          // coalesced flush
        g_cand[(size_t)n * NP + s_base + i] = cbuf[i];
}

// ---------------- kernel F: kr-th largest among candidates + final output ----------------
__global__ void k_sel2(float* out, int out_size) {   // 64 blocks x 256 threads
    const int n = blockIdx.x, tid = threadIdx.x;
    const int ncand = g_cnt[n];
    const int B = g_selB[n];
    int kr = g_selkr[n];

    __shared__ int hist[256];
    __shared__ unsigned s_pref; __shared__ int s_kr;

    unsigned prefix = (unsigned)B;            // top-12 bits established
    const int shifts[3] = {12, 4, 0};
    const int widths[3] = {8, 8, 4};
    for (int pass = 0; pass < 3; pass++) {
        const int sh = shifts[pass], wd = widths[pass];
        const unsigned mask = (1u << wd) - 1u;
        if (tid < 256) hist[tid] = 0;
        __syncthreads();
        for (int i = tid; i < ncand; i += 256) {
            unsigned bits = __float_as_uint(g_cand[(size_t)n * NP + i]);
            if ((bits >> (sh + wd)) == prefix)
                atomicAdd(&hist[(bits >> sh) & mask], 1);
        }
        __syncthreads();
        if (tid == 0) {
            int acc = 0, d = (int)mask;
            for (; d > 0; d--) { if (acc + hist[d] >= kr) break; acc += hist[d]; }
            s_pref = (prefix << wd) | (unsigned)d;
            s_kr   = kr - acc;
        }
        __syncthreads();
        prefix = s_pref; kr = s_kr;
        __syncthreads();
    }

    const float u = __uint_as_float(prefix);
    float sum_gt = 0.0f;
    for (int i = tid; i < ncand; i += 256) {
        float f = g_cand[(size_t)n * NP + i];
        if (f > u) sum_gt += f;
    }
#pragma unroll
    for (int o = 16; o; o >>= 1)
        sum_gt += __shfl_down_sync(0xFFFFFFFFu, sum_gt, o);
    __shared__ float s_sg;
    __shared__ bool s_last;
    if (tid == 0) s_sg = 0.0f;
    __syncthreads();
    if ((tid & 31) == 0 && sum_gt != 0.0f) atomicAdd(&s_sg, sum_gt);
    __syncthreads();
    if (tid == 0) {
        double S = g_sumhi[n] + (double)s_sg + (double)kr * (double)u;
        atomicAdd(&g_loss_c, S);
        __threadfence();
        unsigned d = atomicAdd(&g_done, 1u);
        s_last = (d == NB - 1);
    }
    __syncthreads();
    if (s_last && tid == 0) {                 // last block finalizes
        int ntot = 0;
        for (int i = 0; i < NB; i++) ntot += g_num_pos[i];
        double nf = (double)ntot;
        out[0] = (float)(g_loss_l / nf);
        if (out_size > 1) out[1] = (float)(g_loss_c / nf);
    }
}

// ---------------- launch ----------------
extern "C" void kernel_launch(void* const* d_in, const int* in_sizes, int n_in,
                              void* d_out, int out_size) {
    const float* loc     = (const float*)d_in[0];
    const float* conf    = (const float*)d_in[1];
    const float* priors  = (const float*)d_in[2];
    const float* targets = (const float*)d_in[3];
    float* out = (float*)d_out;

    dim3 grid(NBLK, NB);
    k_init<<<(NB * NHB + 255) / 256, 256>>>();
    k_fused<<<grid, TPB>>>(loc, conf, priors, targets);
    k_force<<<2, 1024>>>(loc, conf, priors, targets);
    k_sel<<<NB, 256>>>();
    k_gather<<<dim3(GSEG, NB), 1024>>>();
    k_sel2<<<NB, 256>>>(out, out_size);
}

// round 11
// speedup vs baseline: 2.1275x; 1.6310x over previous
#include <cuda_runtime.h>
#include <cuda_bf16.h>
#include <math.h>

#define NB 64
#define NP 24564
#define NM 16
#define NC 21
#define TPB 256
#define NBLK ((NP + TPB - 1) / TPB)   // 96
#define NHB 4096                      // hist bins (top-12 float bits)
#define GSEG 6                        // gather segments per batch
#define GCH 4096                      // elements per gather block

// ---------------- device scratch ----------------
__device__ unsigned long long g_winner[NB * NM];   // packed (iou_bits<<32)|(~prior)
__device__ float              g_mined[NB * NP];    // mined conf loss (0 at positives)
__device__ unsigned           g_hist[NB * NHB];    // per-batch 12-bit histograms
__device__ float              g_cand[NB * NP];     // threshold-bin candidates
__device__ int                g_cnt[NB];           // candidate counts
__device__ double             g_sumhi[NB];         // sum of values in bins > B
__device__ int                g_selB[NB], g_selkr[NB];
__device__ int                g_num_pos[NB];
__device__ unsigned           g_done;
__device__ double             g_loss_l;
__device__ double             g_loss_c;

// ---------- shared exact-math helpers (identical in k_fused / k_force) ----------
__device__ __forceinline__ void prior_corners(float4 pr, float& x1, float& y1,
                                              float& x2, float& y2, float& pa) {
    float hz = __fmul_rn(pr.z, 0.5f), hw = __fmul_rn(pr.w, 0.5f);
    x1 = __fsub_rn(pr.x, hz); y1 = __fsub_rn(pr.y, hw);
    x2 = __fadd_rn(pr.x, hz); y2 = __fadd_rn(pr.y, hw);
    pa = __fmul_rn(__fsub_rn(x2, x1), __fsub_rn(y2, y1));
}

__device__ __forceinline__ float iou_fast(float px1, float py1, float px2, float py2,
                                          float pa, float4 tb, float ta) {
    float ix = fmaxf(__fsub_rn(fminf(px2, tb.z), fmaxf(px1, tb.x)), 0.0f);
    float iy = fmaxf(__fsub_rn(fminf(py2, tb.w), fmaxf(py1, tb.y)), 0.0f);
    float inter = __fmul_rn(ix, iy);
    float uni = __fsub_rn(__fadd_rn(pa, ta), inter);
    return __fdividef(inter, uni);
}

__device__ __forceinline__ float sl1e(float d) {
    float a = fabsf(d);
    return (a < 1.0f) ? __fmul_rn(0.5f, __fmul_rn(d, d)) : __fsub_rn(a, 0.5f);
}

__device__ __forceinline__ float loc_loss(const float4 lp, const float4 pr, float4 tb) {
    float gx = __fdividef(__fsub_rn(__fmul_rn(__fadd_rn(tb.x, tb.z), 0.5f), pr.x),
                          __fmul_rn(0.1f, pr.z));
    float gy = __fdividef(__fsub_rn(__fmul_rn(__fadd_rn(tb.y, tb.w), 0.5f), pr.y),
                          __fmul_rn(0.1f, pr.w));
    float gw = __fdividef(__logf(__fdividef(__fsub_rn(tb.z, tb.x), pr.z)), 0.2f);
    float gh = __fdividef(__logf(__fdividef(__fsub_rn(tb.w, tb.y), pr.w)), 0.2f);
    return __fadd_rn(__fadd_rn(sl1e(__fsub_rn(lp.x, gx)), sl1e(__fsub_rn(lp.y, gy))),
                     __fadd_rn(sl1e(__fsub_rn(lp.z, gw)), sl1e(__fsub_rn(lp.w, gh))));
}

__device__ __forceinline__ float lse21(const float* v) {
    float mx = v[0];
#pragma unroll
    for (int c = 1; c < NC; c++) mx = fmaxf(mx, v[c]);
    float s = 0.0f;
#pragma unroll
    for (int c = 0; c < NC; c++) s = __fadd_rn(s, __expf(__fsub_rn(v[c], mx)));
    return __fadd_rn(mx, __logf(s));
}

// ---------------- kernel A: init ----------------
__global__ void k_init() {
    int i = blockIdx.x * blockDim.x + threadIdx.x;
    if (i < NB * NHB) g_hist[i] = 0u;
    if (i < NB * NM) g_winner[i] = 0ull;
    if (i < NB) { g_num_pos[i] = 0; g_cnt[i] = 0; g_sumhi[i] = 0.0; }
    if (i == 0) { g_loss_l = 0.0; g_loss_c = 0.0; g_done = 0u; }
}

// ---------------- kernel B: FUSED match + LSE + losses + histogram (R8-exact, NO launch_bounds) ----------------
__global__ void k_fused(const float* __restrict__ loc,
                        const float* __restrict__ conf,
                        const float* __restrict__ priors,
                        const float* __restrict__ targets) {
    const int n   = blockIdx.y;
    const int tid = threadIdx.x;
    const int rb  = blockIdx.x * TPB;
    const int lane = tid & 31;

    __shared__ float4 t_box[NM];
    __shared__ float  t_area[NM], t_lab[NM];
    __shared__ unsigned long long sh_key[NM];
    __shared__ float sbuf[TPB * NC];
    __shared__ float s_ll, s_plc; __shared__ int s_np;

    if (tid < NM) {
        const float* tp = targets + (size_t)(n * NM + tid) * 5;
        float x1 = tp[0], y1 = tp[1], x2 = tp[2], y2 = tp[3];
        t_box[tid] = make_float4(x1, y1, x2, y2);
        t_area[tid] = __fmul_rn(__fsub_rn(x2, x1), __fsub_rn(y2, y1));
        t_lab[tid] = tp[4];
        sh_key[tid] = 0ull;
    }
    if (tid == 0) { s_ll = 0.0f; s_plc = 0.0f; s_np = 0; }

    const int rows = min(TPB, NP - rb);
    const int nf4  = rows * NC / 4;
    const float4* src = (const float4*)(conf + ((size_t)n * NP + rb) * NC);
    float4* dst = (float4*)sbuf;
    for (int i = tid; i < nf4; i += TPB) dst[i] = src[i];
    __syncthreads();

    const int p = rb + tid;
    const bool valid = tid < rows;

    float px1 = 0.f, py1 = 0.f, px2 = 0.f, py2 = 0.f, pa = 1.f;
    if (valid) {
        float4 pr = ((const float4*)priors)[p];
        prior_corners(pr, px1, py1, px2, py2, pa);
    }
    float best_ov = -1.0f; int best_t = 0;
#pragma unroll
    for (int t = 0; t < NM; t++) {
        float iou = 0.0f;
        if (valid) {
            iou = iou_fast(px1, py1, px2, py2, pa, t_box[t], t_area[t]);
            if (iou > best_ov) { best_ov = iou; best_t = t; }
        }
        unsigned b    = __float_as_uint(iou);
        unsigned wmax = __reduce_max_sync(0xFFFFFFFFu, b);
        if (valid && b == wmax && b != 0u) {      // ties resolved by atomicMax key
            atomicMax(&sh_key[t],
                      ((unsigned long long)wmax << 32) |
                      (unsigned long long)(0xFFFFFFFFu - (unsigned)p));
        }
    }

    float local_ll = 0.0f, local_plc = 0.0f;
    int   local_np = 0;
    float mined = 0.0f;
    if (valid) {
        int conf_t = (best_ov < 0.5f) ? 0 : ((int)t_lab[best_t] + 1);
        bool pos = conf_t > 0;

        const float* v = sbuf + tid * NC;
        float lse = lse21(v);
        float lc  = __fsub_rn(lse, v[conf_t]);

        mined = pos ? 0.0f : lc;
        g_mined[(size_t)n * NP + p] = mined;

        if (pos) {
            local_np  = 1;
            local_plc = lc;
            float4 pr = ((const float4*)priors)[p];
            float4 lp = ((const float4*)loc)[(size_t)n * NP + p];
            local_ll = loc_loss(lp, pr, t_box[best_t]);
        }
    }

    {
        unsigned hv = valid ? (__float_as_uint(mined) >> 20) : 0xFFFFu;
        unsigned peers = __match_any_sync(0xFFFFFFFFu, hv);
        if (hv < NHB && lane == (__ffs(peers) - 1))
            atomicAdd(&g_hist[n * NHB + hv], (unsigned)__popc(peers));
    }

#pragma unroll
    for (int o = 16; o; o >>= 1) {
        local_ll  += __shfl_down_sync(0xFFFFFFFFu, local_ll,  o);
        local_plc += __shfl_down_sync(0xFFFFFFFFu, local_plc, o);
        local_np  += __shfl_down_sync(0xFFFFFFFFu, local_np,  o);
    }
    __syncthreads();
    if (lane == 0) {
        if (local_ll  != 0.0f) atomicAdd(&s_ll,  local_ll);
        if (local_plc != 0.0f) atomicAdd(&s_plc, local_plc);
        if (local_np)          atomicAdd(&s_np,  local_np);
    }
    __syncthreads();
    if (tid < NM && sh_key[tid])
        atomicMax(&g_winner[n * NM + tid], sh_key[tid]);
    if (tid == 0) {
        if (s_np)          atomicAdd(&g_num_pos[n], s_np);
        if (s_ll  != 0.0f) atomicAdd(&g_loss_l, (double)s_ll);
        if (s_plc != 0.0f) atomicAdd(&g_loss_c, (double)s_plc);
    }
}

// ---------------- kernel C: forced-match corrections (R8-proven) ----------------
__global__ void k_force(const float* __restrict__ loc,
                        const float* __restrict__ conf,
                        const float* __restrict__ priors,
                        const float* __restrict__ targets) {
    const int tid  = threadIdx.x;
    const int lane = tid & 31;
    const int warp = tid >> 5;
    const int n    = blockIdx.x * 32 + warp;

    __shared__ float4 w_box[32][NM];
    __shared__ float  w_ar[32][NM], w_lb[32][NM];

    if (n < NB && lane < NM) {
        const float* tp = targets + (size_t)(n * NM + lane) * 5;
        float x1 = tp[0], y1 = tp[1], x2 = tp[2], y2 = tp[3];
        w_box[warp][lane] = make_float4(x1, y1, x2, y2);
        w_ar[warp][lane] = __fmul_rn(__fsub_rn(x2, x1), __fsub_rn(y2, y1));
        w_lb[warp][lane] = tp[4];
    }
    __syncwarp();

    float dll = 0.0f, dlc = 0.0f;
    int   dnp = 0;

    if (n < NB && lane < NM) {
        unsigned long long w = g_winner[n * NM + lane];
        unsigned p = 0xFFFFFFFFu - (unsigned)(w & 0xFFFFFFFFull);

        unsigned peers = __match_any_sync(0x0000FFFFu, p);
        bool firstOcc = (lane == (__ffs(peers) - 1));
        bool isLast   = (lane == (31 - __clz(peers)));   // last truth wins

        float4 pr = ((const float4*)priors)[p];
        float px1, py1, px2, py2, pa;
        prior_corners(pr, px1, py1, px2, py2, pa);

        const float* row = conf + ((size_t)n * NP + p) * NC;
        float v[NC];
#pragma unroll
        for (int c = 0; c < NC; c++) v[c] = row[c];
        float lse = lse21(v);

        if (firstOcc) {
            float best_ov = -1.0f; int best_t = 0;
#pragma unroll
            for (int t = 0; t < NM; t++) {
                float iou = iou_fast(px1, py1, px2, py2, pa, w_box[warp][t], w_ar[warp][t]);
                if (iou > best_ov) { best_ov = iou; best_t = t; }
            }
            int conf_t0 = (best_ov < 0.5f) ? 0 : ((int)w_lb[warp][best_t] + 1);
            if (conf_t0 > 0) {
                dlc -= __fsub_rn(lse, v[conf_t0]);
                float4 lp = ((const float4*)loc)[(size_t)n * NP + p];
                dll -= loc_loss(lp, pr, w_box[warp][best_t]);
            } else {
                dnp += 1;
                float lc_old = __fsub_rn(lse, v[0]);
                atomicAdd(&g_hist[n * NHB + (__float_as_uint(lc_old) >> 20)], 0xFFFFFFFFu);
                atomicAdd(&g_hist[n * NHB + 0], 1u);
            }
            g_mined[(size_t)n * NP + p] = 0.0f;
        }
        if (isLast) {
            int ct = (int)w_lb[warp][lane] + 1;
            dlc += __fsub_rn(lse, v[ct]);
            float4 lp = ((const float4*)loc)[(size_t)n * NP + p];
            dll += loc_loss(lp, pr, w_box[warp][lane]);
        }
    }

#pragma unroll
    for (int o = 16; o; o >>= 1) {
        dll += __shfl_down_sync(0xFFFFFFFFu, dll, o);
        dlc += __shfl_down_sync(0xFFFFFFFFu, dlc, o);
        dnp += __shfl_down_sync(0xFFFFFFFFu, dnp, o);
    }
    if (lane == 0 && n < NB) {
        if (dll != 0.0f) atomicAdd(&g_loss_l, (double)dll);
        if (dlc != 0.0f) atomicAdd(&g_loss_c, (double)dlc);
        if (dnp)         atomicAdd(&g_num_pos[n], dnp);
    }
}

// ---------------- kernel D: gather + inline threshold selection ----------------
// Each block redundantly computes (B, kr) from the hist: 4 bins/thread via one
// uint4 load, two-level shfl suffix scan, register bin-walk. Then gathers.
__global__ void k_gather() {     // grid (GSEG, NB) x 1024
    const int n    = blockIdx.y;
    const int tid  = threadIdx.x;
    const int lane = tid & 31;
    const int warp = tid >> 5;

    __shared__ float cbuf[GCH];
    __shared__ int s_cnt, s_base;
    __shared__ double s_sum;
    __shared__ int wsum[32];
    __shared__ int sh_B, sh_kr;

    if (tid == 0) { s_cnt = 0; s_sum = 0.0; sh_B = -1; sh_kr = 0; }
    __syncthreads();

    // ---- selection phase ----
    const int k = min(3 * g_num_pos[n], NP - 1);
    uint4 hb = ((const uint4*)(g_hist + n * NHB))[tid];   // bins [4*tid, 4*tid+3]
    const int pme = (int)(hb.x + hb.y + hb.z + hb.w);
    int s = pme;
#pragma unroll
    for (int o = 1; o < 32; o <<= 1) {                     // intra-warp suffix sum
        int t = __shfl_down_sync(0xFFFFFFFFu, s, o);
        if (lane + o < 32) s += t;
    }
    if (lane == 0) wsum[warp] = s;
    __syncthreads();
    if (warp == 0) {
        int ws = wsum[lane];
#pragma unroll
        for (int o = 1; o < 32; o <<= 1) {                 // suffix over warps
            int t = __shfl_down_sync(0xFFFFFFFFu, ws, o);
            if (lane + o < 32) ws += t;
        }
        wsum[lane] = ws;                                   // wsum[w] = Σ_{w'>=w}
    }
    __syncthreads();
    {
        int beyond = ((warp < 31) ? wsum[warp + 1] : 0) + (s - pme);
        unsigned hv[4] = {hb.x, hb.y, hb.z, hb.w};
        int running = beyond;                              // count in bins > mine
#pragma unroll
        for (int j = 3; j >= 0; j--) {
            int h = (int)hv[j];
            if (h && running < k && running + h >= k) {    // unique thread hits
                sh_B = tid * 4 + j; sh_kr = k - running;
            }
            running += h;
        }
    }
    __syncthreads();
    const int B = sh_B;
    if (blockIdx.x == 0 && tid == 0) { g_selB[n] = B; g_selkr[n] = sh_kr; }

    // ---- gather phase ----
    if (B >= 0) {
        const int start = blockIdx.x * GCH;
        const int end   = min(start + GCH, NP);
        double local = 0.0;
        for (int i = start + tid; i < end; i += 1024) {
            float f = g_mined[(size_t)n * NP + i];
            unsigned b = __float_as_uint(f) >> 20;
            if ((int)b > B) local += (double)f;
            else if ((int)b == B) {
                int idx = atomicAdd(&s_cnt, 1);           // SMEM atomic (cheap)
                cbuf[idx] = f;
            }
        }
#pragma unroll
        for (int o = 16; o; o >>= 1)
            local += __shfl_down_sync(0xFFFFFFFFu, local, o);
        if (lane == 0 && local != 0.0) atomicAdd(&s_sum, local);
        __syncthreads();

        if (tid == 0) {
            if (s_sum != 0.0) atomicAdd(&g_sumhi[n], s_sum);
            s_base = (s_cnt > 0) ? atomicAdd(&g_cnt[n], s_cnt) : 0;  // ONE global atomic
        }
        __syncthreads();
        for (int i = tid; i < s_cnt; i += 1024)           // coalesced flush
            g_cand[(size_t)n * NP + s_base + i] = cbuf[i];
    }
}

// ---------------- kernel E: kr-th largest among candidates + final output ----------------
__global__ void k_sel2(float* out, int out_size) {   // 64 blocks x 256 threads
    const int n = blockIdx.x, tid = threadIdx.x;
    const int ncand = g_cnt[n];
    const int B = g_selB[n];
    int kr = g_selkr[n];

    __shared__ int hist[256];
    __shared__ unsigned s_pref; __shared__ int s_kr;
    __shared__ float s_sg;
    __shared__ bool s_last;

    if (B >= 0) {
        unsigned prefix = (unsigned)B;            // top-12 bits established
        const int shifts[3] = {12, 4, 0};
        const int widths[3] = {8, 8, 4};
        for (int pass = 0; pass < 3; pass++) {
            const int sh = shifts[pass], wd = widths[pass];
            const unsigned mask = (1u << wd) - 1u;
            if (tid < 256) hist[tid] = 0;
            __syncthreads();
            for (int i = tid; i < ncand; i += 256) {
                unsigned bits = __float_as_uint(g_cand[(size_t)n * NP + i]);
                if ((bits >> (sh + wd)) == prefix)
                    atomicAdd(&hist[(bits >> sh) & mask], 1);
            }
            __syncthreads();
            if (tid == 0) {
                int acc = 0, d = (int)mask;
                for (; d > 0; d--) { if (acc + hist[d] >= kr) break; acc += hist[d]; }
                s_pref = (prefix << wd) | (unsigned)d;
                s_kr   = kr - acc;
            }
            __syncthreads();
            prefix = s_pref; kr = s_kr;
            __syncthreads();
        }

        const float u = __uint_as_float(prefix);
        float sum_gt = 0.0f;
        for (int i = tid; i < ncand; i += 256) {
            float f = g_cand[(size_t)n * NP + i];
            if (f > u) sum_gt += f;
        }
#pragma unroll
        for (int o = 16; o; o >>= 1)
            sum_gt += __shfl_down_sync(0xFFFFFFFFu, sum_gt, o);
        if (tid == 0) s_sg = 0.0f;
        __syncthreads();
        if ((tid & 31) == 0 && sum_gt != 0.0f) atomicAdd(&s_sg, sum_gt);
        __syncthreads();
        if (tid == 0) {
            double S = g_sumhi[n] + (double)s_sg + (double)kr * (double)u;
            atomicAdd(&g_loss_c, S);
        }
    }

    if (tid == 0) {
        __threadfence();
        unsigned d = atomicAdd(&g_done, 1u);
        s_last = (d == NB - 1);
    }
    __syncthreads();
    if (s_last && tid == 0) {                 // last block finalizes
        int ntot = 0;
        for (int i = 0; i < NB; i++) ntot += g_num_pos[i];
        double nf = (double)ntot;
        out[0] = (float)(g_loss_l / nf);
        if (out_size > 1) out[1] = (float)(g_loss_c / nf);
    }
}

// ---------------- launch ----------------
extern "C" void kernel_launch(void* const* d_in, const int* in_sizes, int n_in,
                              void* d_out, int out_size) {
    const float* loc     = (const float*)d_in[0];
    const float* conf    = (const float*)d_in[1];
    const float* priors  = (const float*)d_in[2];
    const float* targets = (const float*)d_in[3];
    float* out = (float*)d_out;

    dim3 grid(NBLK, NB);
    k_init<<<(NB * NHB + 255) / 256, 256>>>();
    k_fused<<<grid, TPB>>>(loc, conf, priors, targets);
    k_force<<<2, 1024>>>(loc, conf, priors, targets);
    k_gather<<<dim3(GSEG, NB), 1024>>>();
    k_sel2<<<NB, 256>>>(out, out_size);
}

// round 12
// speedup vs baseline: 2.6755x; 1.2576x over previous
#include <cuda_runtime.h>
#include <cuda_bf16.h>
#include <math.h>

#define NB 64
#define NP 24564
#define NM 16
#define NC 21
#define TPB 256
#define NBLK ((NP + TPB - 1) / TPB)   // 96

// ---------------- device scratch ----------------
__device__ unsigned long long g_winner[NB * NM];   // packed (iou_bits<<32)|(~prior)
__device__ float              g_mined[NB * NP];    // mined conf loss (0 at positives)
__device__ int                g_num_pos[NB];
__device__ unsigned           g_done;
__device__ double             g_loss_l;
__device__ double             g_loss_c;

// ---------- shared exact-math helpers (identical in k_fused / k_force) ----------
__device__ __forceinline__ void prior_corners(float4 pr, float& x1, float& y1,
                                              float& x2, float& y2, float& pa) {
    float hz = __fmul_rn(pr.z, 0.5f), hw = __fmul_rn(pr.w, 0.5f);
    x1 = __fsub_rn(pr.x, hz); y1 = __fsub_rn(pr.y, hw);
    x2 = __fadd_rn(pr.x, hz); y2 = __fadd_rn(pr.y, hw);
    pa = __fmul_rn(__fsub_rn(x2, x1), __fsub_rn(y2, y1));
}

__device__ __forceinline__ float iou_fast(float px1, float py1, float px2, float py2,
                                          float pa, float4 tb, float ta) {
    float ix = fmaxf(__fsub_rn(fminf(px2, tb.z), fmaxf(px1, tb.x)), 0.0f);
    float iy = fmaxf(__fsub_rn(fminf(py2, tb.w), fmaxf(py1, tb.y)), 0.0f);
    float inter = __fmul_rn(ix, iy);
    float uni = __fsub_rn(__fadd_rn(pa, ta), inter);
    return __fdividef(inter, uni);
}

__device__ __forceinline__ float sl1e(float d) {
    float a = fabsf(d);
    return (a < 1.0f) ? __fmul_rn(0.5f, __fmul_rn(d, d)) : __fsub_rn(a, 0.5f);
}

__device__ __forceinline__ float loc_loss(const float4 lp, const float4 pr, float4 tb) {
    float gx = __fdividef(__fsub_rn(__fmul_rn(__fadd_rn(tb.x, tb.z), 0.5f), pr.x),
                          __fmul_rn(0.1f, pr.z));
    float gy = __fdividef(__fsub_rn(__fmul_rn(__fadd_rn(tb.y, tb.w), 0.5f), pr.y),
                          __fmul_rn(0.1f, pr.w));
    float gw = __fdividef(__logf(__fdividef(__fsub_rn(tb.z, tb.x), pr.z)), 0.2f);
    float gh = __fdividef(__logf(__fdividef(__fsub_rn(tb.w, tb.y), pr.w)), 0.2f);
    return __fadd_rn(__fadd_rn(sl1e(__fsub_rn(lp.x, gx)), sl1e(__fsub_rn(lp.y, gy))),
                     __fadd_rn(sl1e(__fsub_rn(lp.z, gw)), sl1e(__fsub_rn(lp.w, gh))));
}

__device__ __forceinline__ float lse21(const float* v) {
    float mx = v[0];
#pragma unroll
    for (int c = 1; c < NC; c++) mx = fmaxf(mx, v[c]);
    float s = 0.0f;
#pragma unroll
    for (int c = 0; c < NC; c++) s = __fadd_rn(s, __expf(__fsub_rn(v[c], mx)));
    return __fadd_rn(mx, __logf(s));
}

// ---------------- kernel A: init (tiny now — no hist) ----------------
__global__ void k_init() {
    int i = blockIdx.x * blockDim.x + threadIdx.x;
    if (i < NB * NM) g_winner[i] = 0ull;
    if (i < NB) g_num_pos[i] = 0;
    if (i == 0) { g_loss_l = 0.0; g_loss_c = 0.0; g_done = 0u; }
}

// ---------------- kernel B: FUSED match + LSE + losses (R11-proven, hist removed) ----------------
__global__ void k_fused(const float* __restrict__ loc,
                        const float* __restrict__ conf,
                        const float* __restrict__ priors,
                        const float* __restrict__ targets) {
    const int n   = blockIdx.y;
    const int tid = threadIdx.x;
    const int rb  = blockIdx.x * TPB;
    const int lane = tid & 31;

    __shared__ float4 t_box[NM];
    __shared__ float  t_area[NM], t_lab[NM];
    __shared__ unsigned long long sh_key[NM];
    __shared__ float sbuf[TPB * NC];
    __shared__ float s_ll, s_plc; __shared__ int s_np;

    if (tid < NM) {
        const float* tp = targets + (size_t)(n * NM + tid) * 5;
        float x1 = tp[0], y1 = tp[1], x2 = tp[2], y2 = tp[3];
        t_box[tid] = make_float4(x1, y1, x2, y2);
        t_area[tid] = __fmul_rn(__fsub_rn(x2, x1), __fsub_rn(y2, y1));
        t_lab[tid] = tp[4];
        sh_key[tid] = 0ull;
    }
    if (tid == 0) { s_ll = 0.0f; s_plc = 0.0f; s_np = 0; }

    const int rows = min(TPB, NP - rb);
    const int nf4  = rows * NC / 4;
    const float4* src = (const float4*)(conf + ((size_t)n * NP + rb) * NC);
    float4* dst = (float4*)sbuf;
    for (int i = tid; i < nf4; i += TPB) dst[i] = src[i];
    __syncthreads();

    const int p = rb + tid;
    const bool valid = tid < rows;

    float px1 = 0.f, py1 = 0.f, px2 = 0.f, py2 = 0.f, pa = 1.f;
    if (valid) {
        float4 pr = ((const float4*)priors)[p];
        prior_corners(pr, px1, py1, px2, py2, pa);
    }
    float best_ov = -1.0f; int best_t = 0;
#pragma unroll
    for (int t = 0; t < NM; t++) {
        float iou = 0.0f;
        if (valid) {
            iou = iou_fast(px1, py1, px2, py2, pa, t_box[t], t_area[t]);
            if (iou > best_ov) { best_ov = iou; best_t = t; }
        }
        unsigned b    = __float_as_uint(iou);
        unsigned wmax = __reduce_max_sync(0xFFFFFFFFu, b);
        if (valid && b == wmax && b != 0u) {      // ties resolved by atomicMax key
            atomicMax(&sh_key[t],
                      ((unsigned long long)wmax << 32) |
                      (unsigned long long)(0xFFFFFFFFu - (unsigned)p));
        }
    }

    float local_ll = 0.0f, local_plc = 0.0f;
    int   local_np = 0;
    if (valid) {
        int conf_t = (best_ov < 0.5f) ? 0 : ((int)t_lab[best_t] + 1);
        bool pos = conf_t > 0;

        const float* v = sbuf + tid * NC;
        float lse = lse21(v);
        float lc  = __fsub_rn(lse, v[conf_t]);

        g_mined[(size_t)n * NP + p] = pos ? 0.0f : lc;

        if (pos) {
            local_np  = 1;
            local_plc = lc;
            float4 pr = ((const float4*)priors)[p];
            float4 lp = ((const float4*)loc)[(size_t)n * NP + p];
            local_ll = loc_loss(lp, pr, t_box[best_t]);
        }
    }

#pragma unroll
    for (int o = 16; o; o >>= 1) {
        local_ll  += __shfl_down_sync(0xFFFFFFFFu, local_ll,  o);
        local_plc += __shfl_down_sync(0xFFFFFFFFu, local_plc, o);
        local_np  += __shfl_down_sync(0xFFFFFFFFu, local_np,  o);
    }
    __syncthreads();
    if (lane == 0) {
        if (local_ll  != 0.0f) atomicAdd(&s_ll,  local_ll);
        if (local_plc != 0.0f) atomicAdd(&s_plc, local_plc);
        if (local_np)          atomicAdd(&s_np,  local_np);
    }
    __syncthreads();
    if (tid < NM && sh_key[tid])
        atomicMax(&g_winner[n * NM + tid], sh_key[tid]);
    if (tid == 0) {
        if (s_np)          atomicAdd(&g_num_pos[n], s_np);
        if (s_ll  != 0.0f) atomicAdd(&g_loss_l, (double)s_ll);
        if (s_plc != 0.0f) atomicAdd(&g_loss_c, (double)s_plc);
    }
}

// ---------------- kernel C: forced-match corrections (R11-proven, hist fixups removed) ----------------
__global__ void k_force(const float* __restrict__ loc,
                        const float* __restrict__ conf,
                        const float* __restrict__ priors,
                        const float* __restrict__ targets) {
    const int tid  = threadIdx.x;
    const int lane = tid & 31;
    const int warp = tid >> 5;
    const int n    = blockIdx.x * 32 + warp;

    __shared__ float4 w_box[32][NM];
    __shared__ float  w_ar[32][NM], w_lb[32][NM];

    if (n < NB && lane < NM) {
        const float* tp = targets + (size_t)(n * NM + lane) * 5;
        float x1 = tp[0], y1 = tp[1], x2 = tp[2], y2 = tp[3];
        w_box[warp][lane] = make_float4(x1, y1, x2, y2);
        w_ar[warp][lane] = __fmul_rn(__fsub_rn(x2, x1), __fsub_rn(y2, y1));
        w_lb[warp][lane] = tp[4];
    }
    __syncwarp();

    float dll = 0.0f, dlc = 0.0f;
    int   dnp = 0;

    if (n < NB && lane < NM) {
        unsigned long long w = g_winner[n * NM + lane];
        unsigned p = 0xFFFFFFFFu - (unsigned)(w & 0xFFFFFFFFull);

        unsigned peers = __match_any_sync(0x0000FFFFu, p);
        bool firstOcc = (lane == (__ffs(peers) - 1));
        bool isLast   = (lane == (31 - __clz(peers)));   // last truth wins

        float4 pr = ((const float4*)priors)[p];
        float px1, py1, px2, py2, pa;
        prior_corners(pr, px1, py1, px2, py2, pa);

        const float* row = conf + ((size_t)n * NP + p) * NC;
        float v[NC];
#pragma unroll
        for (int c = 0; c < NC; c++) v[c] = row[c];
        float lse = lse21(v);

        if (firstOcc) {
            float best_ov = -1.0f; int best_t = 0;
#pragma unroll
            for (int t = 0; t < NM; t++) {
                float iou = iou_fast(px1, py1, px2, py2, pa, w_box[warp][t], w_ar[warp][t]);
                if (iou > best_ov) { best_ov = iou; best_t = t; }
            }
            int conf_t0 = (best_ov < 0.5f) ? 0 : ((int)w_lb[warp][best_t] + 1);
            if (conf_t0 > 0) {
                dlc -= __fsub_rn(lse, v[conf_t0]);
                float4 lp = ((const float4*)loc)[(size_t)n * NP + p];
                dll -= loc_loss(lp, pr, w_box[warp][best_t]);
            } else {
                dnp += 1;                 // becomes positive
            }
            g_mined[(size_t)n * NP + p] = 0.0f;
        }
        if (isLast) {
            int ct = (int)w_lb[warp][lane] + 1;
            dlc += __fsub_rn(lse, v[ct]);
            float4 lp = ((const float4*)loc)[(size_t)n * NP + p];
            dll += loc_loss(lp, pr, w_box[warp][lane]);
        }
    }

#pragma unroll
    for (int o = 16; o; o >>= 1) {
        dll += __shfl_down_sync(0xFFFFFFFFu, dll, o);
        dlc += __shfl_down_sync(0xFFFFFFFFu, dlc, o);
        dnp += __shfl_down_sync(0xFFFFFFFFu, dnp, o);
    }
    if (lane == 0 && n < NB) {
        if (dll != 0.0f) atomicAdd(&g_loss_l, (double)dll);
        if (dlc != 0.0f) atomicAdd(&g_loss_c, (double)dlc);
        if (dnp)         atomicAdd(&g_num_pos[n], dnp);
    }
}

// ---------------- kernel D: register-resident exact top-k sum + finalize ----------------
// One block per batch. 24 values/thread in registers; 32-round binary search on
// bit patterns with REDUX-based block counts; then sum(v>u) + (k-cnt)*u.
__global__ void k_topsum(float* out, int out_size) {    // grid NB x 1024
    const int n    = blockIdx.x;
    const int tid  = threadIdx.x;
    const int lane = tid & 31;
    const int warp = tid >> 5;

    __shared__ int   s_wcnt[32];
    __shared__ float s_wsum[32];
    __shared__ int   s_cnt;
    __shared__ bool  s_last;

    // load all 24564 values of this batch into registers (coalesced)
    const float* row = g_mined + (size_t)n * NP;
    unsigned bits[24];
#pragma unroll
    for (int j = 0; j < 23; j++)
        bits[j] = __float_as_uint(row[tid + j * 1024]);
    {
        int i = tid + 23 * 1024;
        bits[23] = (i < NP) ? __float_as_uint(row[i]) : 0u;   // pad: harmless (see analysis)
    }

    const int k = min(3 * g_num_pos[n], NP - 1);

    if (k > 0) {
        // binary search: largest u with count(bits >= u) >= k  → u = k-th largest
        unsigned lo = 0u, hi = 0xFFFFFFFFu;
        while (hi - lo > 1u) {
            unsigned mid = lo + (hi - lo) / 2u;
            int c = 0;
#pragma unroll
            for (int j = 0; j < 24; j++) c += (bits[j] >= mid);
            c = __reduce_add_sync(0xFFFFFFFFu, c);
            if (lane == 0) s_wcnt[warp] = c;
            __syncthreads();
            if (warp == 0) {
                int t = __reduce_add_sync(0xFFFFFFFFu, s_wcnt[lane]);
                if (lane == 0) s_cnt = t;
            }
            __syncthreads();
            if (s_cnt >= k) lo = mid; else hi = mid;
        }
        const unsigned u = lo;

        // sum of strictly-greater + fill remaining slots with the k-th value
        int   cgt = 0;
        float sum = 0.0f;
#pragma unroll
        for (int j = 0; j < 24; j++) {
            unsigned b = bits[j];
            if (b > u) { cgt++; sum += __uint_as_float(b); }
        }
        cgt = __reduce_add_sync(0xFFFFFFFFu, cgt);
#pragma unroll
        for (int o = 16; o; o >>= 1)
            sum += __shfl_down_sync(0xFFFFFFFFu, sum, o);
        if (lane == 0) { s_wcnt[warp] = cgt; s_wsum[warp] = sum; }
        __syncthreads();
        if (warp == 0) {
            int   tc = __reduce_add_sync(0xFFFFFFFFu, s_wcnt[lane]);
            float ts = s_wsum[lane];
#pragma unroll
            for (int o = 16; o; o >>= 1)
                ts += __shfl_down_sync(0xFFFFFFFFu, ts, o);
            if (lane == 0) {
                float S = ts + (float)(k - tc) * __uint_as_float(u);
                atomicAdd(&g_loss_c, (double)S);
            }
        }
    }
    __syncthreads();

    if (tid == 0) {
        __threadfence();
        unsigned d = atomicAdd(&g_done, 1u);
        s_last = (d == NB - 1);
    }
    __syncthreads();
    if (s_last && tid == 0) {                 // last block finalizes
        int ntot = 0;
        for (int i = 0; i < NB; i++) ntot += g_num_pos[i];
        double nf = (double)ntot;
        out[0] = (float)(g_loss_l / nf);
        if (out_size > 1) out[1] = (float)(g_loss_c / nf);
    }
}

// ---------------- launch ----------------
extern "C" void kernel_launch(void* const* d_in, const int* in_sizes, int n_in,
                              void* d_out, int out_size) {
    const float* loc     = (const float*)d_in[0];
    const float* conf    = (const float*)d_in[1];
    const float* priors  = (const float*)d_in[2];
    const float* targets = (const float*)d_in[3];
    float* out = (float*)d_out;

    dim3 grid(NBLK, NB);
    k_init<<<4, 256>>>();
    k_fused<<<grid, TPB>>>(loc, conf, priors, targets);
    k_force<<<2, 1024>>>(loc, conf, priors, targets);
    k_topsum<<<NB, 1024>>>(out, out_size);
}

// round 13
// speedup vs baseline: 2.6899x; 1.0054x over previous
#include <cuda_runtime.h>
#include <cuda_bf16.h>
#include <math.h>

#define NB 64
#define NP 24564
#define NM 16
#define NC 21
#define TPB 256
#define NBLK ((NP + TPB - 1) / TPB)   // 96

// ---------------- device scratch ----------------
__device__ unsigned long long g_winner[NB * NM];   // packed (iou_bits<<32)|(~prior)
__device__ float              g_mined[NB * NP];    // mined conf loss (0 at positives)
__device__ int                g_num_pos[NB];
__device__ unsigned           g_done;
__device__ double             g_loss_l;
__device__ double             g_loss_c;

// ---------- cp.async helpers ----------
__device__ __forceinline__ void cp_async16(void* smem, const void* gmem) {
    unsigned s = (unsigned)__cvta_generic_to_shared(smem);
    asm volatile("cp.async.cg.shared.global [%0], [%1], 16;\n" :: "r"(s), "l"(gmem));
}
#define CP_COMMIT() asm volatile("cp.async.commit_group;\n" ::: "memory")
#define CP_WAIT0()  asm volatile("cp.async.wait_group 0;\n" ::: "memory")

// ---------- shared exact-math helpers (identical in k_fused / k_force) ----------
__device__ __forceinline__ void prior_corners(float4 pr, float& x1, float& y1,
                                              float& x2, float& y2, float& pa) {
    float hz = __fmul_rn(pr.z, 0.5f), hw = __fmul_rn(pr.w, 0.5f);
    x1 = __fsub_rn(pr.x, hz); y1 = __fsub_rn(pr.y, hw);
    x2 = __fadd_rn(pr.x, hz); y2 = __fadd_rn(pr.y, hw);
    pa = __fmul_rn(__fsub_rn(x2, x1), __fsub_rn(y2, y1));
}

__device__ __forceinline__ float iou_fast(float px1, float py1, float px2, float py2,
                                          float pa, float4 tb, float ta) {
    float ix = fmaxf(__fsub_rn(fminf(px2, tb.z), fmaxf(px1, tb.x)), 0.0f);
    float iy = fmaxf(__fsub_rn(fminf(py2, tb.w), fmaxf(py1, tb.y)), 0.0f);
    float inter = __fmul_rn(ix, iy);
    float uni = __fsub_rn(__fadd_rn(pa, ta), inter);
    return __fdividef(inter, uni);
}

__device__ __forceinline__ float sl1e(float d) {
    float a = fabsf(d);
    return (a < 1.0f) ? __fmul_rn(0.5f, __fmul_rn(d, d)) : __fsub_rn(a, 0.5f);
}

__device__ __forceinline__ float loc_loss(const float4 lp, const float4 pr, float4 tb) {
    float gx = __fdividef(__fsub_rn(__fmul_rn(__fadd_rn(tb.x, tb.z), 0.5f), pr.x),
                          __fmul_rn(0.1f, pr.z));
    float gy = __fdividef(__fsub_rn(__fmul_rn(__fadd_rn(tb.y, tb.w), 0.5f), pr.y),
                          __fmul_rn(0.1f, pr.w));
    float gw = __fdividef(__logf(__fdividef(__fsub_rn(tb.z, tb.x), pr.z)), 0.2f);
    float gh = __fdividef(__logf(__fdividef(__fsub_rn(tb.w, tb.y), pr.w)), 0.2f);
    return __fadd_rn(__fadd_rn(sl1e(__fsub_rn(lp.x, gx)), sl1e(__fsub_rn(lp.y, gy))),
                     __fadd_rn(sl1e(__fsub_rn(lp.z, gw)), sl1e(__fsub_rn(lp.w, gh))));
}

__device__ __forceinline__ float lse21(const float* v) {
    float mx = v[0];
#pragma unroll
    for (int c = 1; c < NC; c++) mx = fmaxf(mx, v[c]);
    float s = 0.0f;
#pragma unroll
    for (int c = 0; c < NC; c++) s = __fadd_rn(s, __expf(__fsub_rn(v[c], mx)));
    return __fadd_rn(mx, __logf(s));
}

// ---------------- kernel A: init ----------------
__global__ void k_init() {
    int i = blockIdx.x * blockDim.x + threadIdx.x;
    if (i < NB * NM) g_winner[i] = 0ull;
    if (i < NB) g_num_pos[i] = 0;
    if (i == 0) { g_loss_l = 0.0; g_loss_c = 0.0; g_done = 0u; }
}

// ---------------- kernel B: FUSED match + LSE + losses (cp.async overlap, NO launch_bounds) ----------------
__global__ void k_fused(const float* __restrict__ loc,
                        const float* __restrict__ conf,
                        const float* __restrict__ priors,
                        const float* __restrict__ targets) {
    const int n   = blockIdx.y;
    const int tid = threadIdx.x;
    const int rb  = blockIdx.x * TPB;
    const int lane = tid & 31;

    __shared__ float4 t_box[NM];
    __shared__ float  t_area[NM], t_lab[NM];
    __shared__ unsigned long long sh_key[NM];
    __shared__ __align__(16) float sbuf[TPB * NC];
    __shared__ float s_ll, s_plc; __shared__ int s_np;

    if (tid < NM) {
        const float* tp = targets + (size_t)(n * NM + tid) * 5;
        float x1 = tp[0], y1 = tp[1], x2 = tp[2], y2 = tp[3];
        t_box[tid] = make_float4(x1, y1, x2, y2);
        t_area[tid] = __fmul_rn(__fsub_rn(x2, x1), __fsub_rn(y2, y1));
        t_lab[tid] = tp[4];
        sh_key[tid] = 0ull;
    }
    if (tid == 0) { s_ll = 0.0f; s_plc = 0.0f; s_np = 0; }
    __syncthreads();                       // t_box/sh_key visible

    // issue async conf staging; it flies during the match phase
    const int rows = min(TPB, NP - rb);
    const int nf4  = rows * NC / 4;        // 1344 or 1281 (both exact)
    const float4* src = (const float4*)(conf + ((size_t)n * NP + rb) * NC);
    for (int i = tid; i < nf4; i += TPB)
        cp_async16(((float4*)sbuf) + i, src + i);
    CP_COMMIT();

    const int p = rb + tid;
    const bool valid = tid < rows;

    // ---- match phase (overlaps conf traffic) ----
    float px1 = 0.f, py1 = 0.f, px2 = 0.f, py2 = 0.f, pa = 1.f;
    if (valid) {
        float4 pr = ((const float4*)priors)[p];
        prior_corners(pr, px1, py1, px2, py2, pa);
    }
    float best_ov = -1.0f; int best_t = 0;
#pragma unroll
    for (int t = 0; t < NM; t++) {
        float iou = 0.0f;
        if (valid) {
            iou = iou_fast(px1, py1, px2, py2, pa, t_box[t], t_area[t]);
            if (iou > best_ov) { best_ov = iou; best_t = t; }
        }
        unsigned b    = __float_as_uint(iou);
        unsigned wmax = __reduce_max_sync(0xFFFFFFFFu, b);
        if (valid && b == wmax && b != 0u) {      // ties resolved by atomicMax key
            atomicMax(&sh_key[t],
                      ((unsigned long long)wmax << 32) |
                      (unsigned long long)(0xFFFFFFFFu - (unsigned)p));
        }
    }

    CP_WAIT0();
    __syncthreads();                       // conf staged

    // ---- loss phase ----
    float local_ll = 0.0f, local_plc = 0.0f;
    int   local_np = 0;
    if (valid) {
        int conf_t = (best_ov < 0.5f) ? 0 : ((int)t_lab[best_t] + 1);
        bool pos = conf_t > 0;

        const float* v = sbuf + tid * NC;
        float lse = lse21(v);
        float lc  = __fsub_rn(lse, v[conf_t]);

        g_mined[(size_t)n * NP + p] = pos ? 0.0f : lc;

        if (pos) {
            local_np  = 1;
            local_plc = lc;
            float4 pr = ((const float4*)priors)[p];
            float4 lp = ((const float4*)loc)[(size_t)n * NP + p];
            local_ll = loc_loss(lp, pr, t_box[best_t]);
        }
    }

#pragma unroll
    for (int o = 16; o; o >>= 1) {
        local_ll  += __shfl_down_sync(0xFFFFFFFFu, local_ll,  o);
        local_plc += __shfl_down_sync(0xFFFFFFFFu, local_plc, o);
        local_np  += __shfl_down_sync(0xFFFFFFFFu, local_np,  o);
    }
    __syncthreads();
    if (lane == 0) {
        if (local_ll  != 0.0f) atomicAdd(&s_ll,  local_ll);
        if (local_plc != 0.0f) atomicAdd(&s_plc, local_plc);
        if (local_np)          atomicAdd(&s_np,  local_np);
    }
    __syncthreads();
    if (tid < NM && sh_key[tid])
        atomicMax(&g_winner[n * NM + tid], sh_key[tid]);
    if (tid == 0) {
        if (s_np)          atomicAdd(&g_num_pos[n], s_np);
        if (s_ll  != 0.0f) atomicAdd(&g_loss_l, (double)s_ll);
        if (s_plc != 0.0f) atomicAdd(&g_loss_c, (double)s_plc);
    }
}

// ---------------- kernel C: forced-match corrections (R12-proven) ----------------
__global__ void k_force(const float* __restrict__ loc,
                        const float* __restrict__ conf,
                        const float* __restrict__ priors,
                        const float* __restrict__ targets) {
    const int tid  = threadIdx.x;
    const int lane = tid & 31;
    const int warp = tid >> 5;
    const int n    = blockIdx.x * 32 + warp;

    __shared__ float4 w_box[32][NM];
    __shared__ float  w_ar[32][NM], w_lb[32][NM];

    if (n < NB && lane < NM) {
        const float* tp = targets + (size_t)(n * NM + lane) * 5;
        float x1 = tp[0], y1 = tp[1], x2 = tp[2], y2 = tp[3];
        w_box[warp][lane] = make_float4(x1, y1, x2, y2);
        w_ar[warp][lane] = __fmul_rn(__fsub_rn(x2, x1), __fsub_rn(y2, y1));
        w_lb[warp][lane] = tp[4];
    }
    __syncwarp();

    float dll = 0.0f, dlc = 0.0f;
    int   dnp = 0;

    if (n < NB && lane < NM) {
        unsigned long long w = g_winner[n * NM + lane];
        unsigned p = 0xFFFFFFFFu - (unsigned)(w & 0xFFFFFFFFull);

        unsigned peers = __match_any_sync(0x0000FFFFu, p);
        bool firstOcc = (lane == (__ffs(peers) - 1));
        bool isLast   = (lane == (31 - __clz(peers)));   // last truth wins

        float4 pr = ((const float4*)priors)[p];
        float px1, py1, px2, py2, pa;
        prior_corners(pr, px1, py1, px2, py2, pa);

        const float* row = conf + ((size_t)n * NP + p) * NC;
        float v[NC];
#pragma unroll
        for (int c = 0; c < NC; c++) v[c] = row[c];
        float lse = lse21(v);

        if (firstOcc) {
            float best_ov = -1.0f; int best_t = 0;
#pragma unroll
            for (int t = 0; t < NM; t++) {
                float iou = iou_fast(px1, py1, px2, py2, pa, w_box[warp][t], w_ar[warp][t]);
                if (iou > best_ov) { best_ov = iou; best_t = t; }
            }
            int conf_t0 = (best_ov < 0.5f) ? 0 : ((int)w_lb[warp][best_t] + 1);
            if (conf_t0 > 0) {
                dlc -= __fsub_rn(lse, v[conf_t0]);
                float4 lp = ((const float4*)loc)[(size_t)n * NP + p];
                dll -= loc_loss(lp, pr, w_box[warp][best_t]);
            } else {
                dnp += 1;                 // becomes positive
            }
            g_mined[(size_t)n * NP + p] = 0.0f;
        }
        if (isLast) {
            int ct = (int)w_lb[warp][lane] + 1;
            dlc += __fsub_rn(lse, v[ct]);
            float4 lp = ((const float4*)loc)[(size_t)n * NP + p];
            dll += loc_loss(lp, pr, w_box[warp][lane]);
        }
    }

#pragma unroll
    for (int o = 16; o; o >>= 1) {
        dll += __shfl_down_sync(0xFFFFFFFFu, dll, o);
        dlc += __shfl_down_sync(0xFFFFFFFFu, dlc, o);
        dnp += __shfl_down_sync(0xFFFFFFFFu, dnp, o);
    }
    if (lane == 0 && n < NB) {
        if (dll != 0.0f) atomicAdd(&g_loss_l, (double)dll);
        if (dlc != 0.0f) atomicAdd(&g_loss_c, (double)dlc);
        if (dnp)         atomicAdd(&g_num_pos[n], dnp);
    }
}

// ---------------- kernel D: register top-k sum, 4-way search + finalize ----------------
__global__ void k_topsum(float* out, int out_size) {    // grid NB x 1024
    const int n    = blockIdx.x;
    const int tid  = threadIdx.x;
    const int lane = tid & 31;
    const int warp = tid >> 5;

    __shared__ unsigned s_w1[32], s_w2[32];
    __shared__ unsigned s_c1, s_c2, s_c3;
    __shared__ unsigned s_max;
    __shared__ float    s_wsum[32];
    __shared__ bool     s_last;

    // vectorized load: 6141 uint4 = 24564 floats exactly; 3 threads pad at j=5
    const uint4* row4 = (const uint4*)(g_mined + (size_t)n * NP);
    unsigned bits[24];
#pragma unroll
    for (int j = 0; j < 6; j++) {
        int i = tid + j * 1024;
        uint4 v = (i < 6141) ? row4[i] : make_uint4(0u, 0u, 0u, 0u);
        bits[j * 4 + 0] = v.x; bits[j * 4 + 1] = v.y;
        bits[j * 4 + 2] = v.z; bits[j * 4 + 3] = v.w;
    }

    const int k = min(3 * g_num_pos[n], NP - 1);

    if (k > 0) {
        // block max -> clamp search range
        unsigned mx = 0u;
#pragma unroll
        for (int j = 0; j < 24; j++) mx = max(mx, bits[j]);
        mx = __reduce_max_sync(0xFFFFFFFFu, mx);
        if (lane == 0) s_w1[warp] = mx;
        __syncthreads();
        if (warp == 0) {
            unsigned m = __reduce_max_sync(0xFFFFFFFFu, s_w1[lane]);
            if (lane == 0) s_max = m;
        }
        __syncthreads();

        // invariant: count(>=lo) >= k, count(>=hi) < k
        unsigned lo = 0u, hi = s_max + 1u;
        while (hi - lo > 1u) {
            unsigned span = hi - lo;
            if (span >= 4u) {
                unsigned st = span >> 2;
                unsigned m1 = lo + st, m2 = lo + 2u * st, m3 = lo + 3u * st;
                unsigned c1 = 0, c2 = 0, c3 = 0;
#pragma unroll
                for (int j = 0; j < 24; j++) {
                    unsigned b = bits[j];
                    c1 += (b >= m1); c2 += (b >= m2); c3 += (b >= m3);
                }
                unsigned p1 = __reduce_add_sync(0xFFFFFFFFu, c1 | (c2 << 16));
                unsigned p2 = __reduce_add_sync(0xFFFFFFFFu, c3);
                if (lane == 0) { s_w1[warp] = p1; s_w2[warp] = p2; }
                __syncthreads();
                if (warp == 0) {
                    unsigned t1 = __reduce_add_sync(0xFFFFFFFFu, s_w1[lane]);
                    unsigned t2 = __reduce_add_sync(0xFFFFFFFFu, s_w2[lane]);
                    if (lane == 0) {
                        s_c1 = t1 & 0xFFFFu; s_c2 = t1 >> 16; s_c3 = t2;
                    }
                }
                __syncthreads();
                unsigned C1 = s_c1, C2 = s_c2, C3 = s_c3;
                if      (C3 >= (unsigned)k) lo = m3;
                else if (C2 >= (unsigned)k) { lo = m2; hi = m3; }
                else if (C1 >= (unsigned)k) { lo = m1; hi = m2; }
                else                        hi = m1;
            } else {
                unsigned m = lo + (span >> 1);
                unsigned c = 0;
#pragma unroll
                for (int j = 0; j < 24; j++) c += (bits[j] >= m);
                c = __reduce_add_sync(0xFFFFFFFFu, c);
                if (lane == 0) s_w1[warp] = c;
                __syncthreads();
                if (warp == 0) {
                    unsigned t = __reduce_add_sync(0xFFFFFFFFu, s_w1[lane]);
                    if (lane == 0) s_c1 = t;
                }
                __syncthreads();
                if (s_c1 >= (unsigned)k) lo = m; else hi = m;
            }
        }
        const unsigned u = lo;

        // sum of strictly-greater + fill remaining slots with the k-th value
        unsigned cgt = 0;
        float sum = 0.0f;
#pragma unroll
        for (int j = 0; j < 24; j++) {
            unsigned b = bits[j];
            if (b > u) { cgt++; sum += __uint_as_float(b); }
        }
        cgt = __reduce_add_sync(0xFFFFFFFFu, cgt);
#pragma unroll
        for (int o = 16; o; o >>= 1)
            sum += __shfl_down_sync(0xFFFFFFFFu, sum, o);
        if (lane == 0) { s_w1[warp] = cgt; s_wsum[warp] = sum; }
        __syncthreads();
        if (warp == 0) {
            unsigned tc = __reduce_add_sync(0xFFFFFFFFu, s_w1[lane]);
            float ts = s_wsum[lane];
#pragma unroll
            for (int o = 16; o; o >>= 1)
                ts += __shfl_down_sync(0xFFFFFFFFu, ts, o);
            if (lane == 0) {
                float S = ts + (float)(int)((unsigned)k - tc) * __uint_as_float(u);
                atomicAdd(&g_loss_c, (double)S);
            }
        }
    }
    __syncthreads();

    if (tid == 0) {
        __threadfence();
        unsigned d = atomicAdd(&g_done, 1u);
        s_last = (d == NB - 1);
    }
    __syncthreads();
    if (s_last && tid == 0) {                 // last block finalizes
        int ntot = 0;
        for (int i = 0; i < NB; i++) ntot += g_num_pos[i];
        double nf = (double)ntot;
        out[0] = (float)(g_loss_l / nf);
        if (out_size > 1) out[1] = (float)(g_loss_c / nf);
    }
}

// ---------------- launch ----------------
extern "C" void kernel_launch(void* const* d_in, const int* in_sizes, int n_in,
                              void* d_out, int out_size) {
    const float* loc     = (const float*)d_in[0];
    const float* conf    = (const float*)d_in[1];
    const float* priors  = (const float*)d_in[2];
    const float* targets = (const float*)d_in[3];
    float* out = (float*)d_out;

    dim3 grid(NBLK, NB);
    k_init<<<4, 256>>>();
    k_fused<<<grid, TPB>>>(loc, conf, priors, targets);
    k_force<<<2, 1024>>>(loc, conf, priors, targets);
    k_topsum<<<NB, 1024>>>(out, out_size);
}